// round 8
// baseline (speedup 1.0000x reference)
#include <cuda_runtime.h>
#include <cstdint>

// RandomTimeMask: out[n,c,l] = x[n,c,l] if ((l - starts[n,c]) mod L) >= L/4 else 0
// x [128,12,32768] fp32, starts [128,12] int32. L=32768, mask_len=8192.
//
// R8: fully unrolled, branch-free body. Each thread owns exactly 2 paired
// iterations (6 copy-loads + 8 stores incl. 2 zero stores); all 6 LDG.128
// are front-batched before any STG (MLP_p1=6). The single ragged index in
// split 3 is CLAMPED (idempotent duplicate write) instead of branched.
// App traffic stays at the 336 MB minimum (144R + 192W).

static constexpr int L    = 32768;
static constexpr int ML   = 8192;         // mask_len
static constexpr int LM1  = L - 1;
static constexpr int VPR  = L / 4;        // 8192 float4 per row
static constexpr int VM1  = VPR - 1;      // 8191
static constexpr int THREADS = 256;
static constexpr int SPLITS  = 4;         // blocks per row
static constexpr int JTOT    = 2047;      // paired iterations per row
static constexpr int JSPAN   = 512;       // JTOT span per split (last is 511)

__global__ __launch_bounds__(THREADS)
void random_time_mask_kernel(const float4* __restrict__ x,
                             const int* __restrict__ starts,
                             float4* __restrict__ out)
{
    const int row   = blockIdx.x >> 2;           // 0..1535
    const int split = blockIdx.x & 3;            // 0..3
    const int s     = __ldg(&starts[row]);       // 0 <= s < L

    const float4* __restrict__ xr = x   + (size_t)row * VPR;
    float4*       __restrict__ yr = out + (size_t)row * VPR;

    const int b0 = s >> 2;                       // first (possibly partial) masked vec
    const int b1 = (b0 + 2048) & VM1;            // vec containing mask end
    const int k0 = (b1 + 1) & VM1;               // kept stream base

    // Two paired iterations per thread; j1 clamped (duplicate write is idempotent).
    const int j0 = split * JSPAN + threadIdx.x;
    const int j1 = min(j0 + THREADS, JTOT - 1);

    const int mza = (b0 + 1 + j0)    & VM1;
    const int c0a = (k0 + j0)        & VM1;
    const int c1a = (k0 + 2047 + j0) & VM1;
    const int c2a = (k0 + 4094 + j0) & VM1;
    const int mzb = (b0 + 1 + j1)    & VM1;
    const int c0b = (k0 + j1)        & VM1;
    const int c1b = (k0 + 2047 + j1) & VM1;
    const int c2b = (k0 + 4094 + j1) & VM1;

    // Front-batch all 6 loads.
    const float4 v0a = xr[c0a];
    const float4 v1a = xr[c1a];
    const float4 v2a = xr[c2a];
    const float4 v0b = xr[c0b];
    const float4 v1b = xr[c1b];
    const float4 v2b = xr[c2b];

    const float4 z = make_float4(0.f, 0.f, 0.f, 0.f);
    yr[mza] = z;
    yr[c0a] = v0a;
    yr[c1a] = v1a;
    yr[c2a] = v2a;
    yr[mzb] = z;
    yr[c0b] = v0b;
    yr[c1b] = v1b;
    yr[c2b] = v2b;

    // Edge vectors (4 per row): boundary vecs b0, b1 (partial mask) and the
    // 2 kept remainder vecs. Full per-lane select path.
    if (split == 0 && threadIdx.x < 4) {
        const int t = threadIdx.x;
        const int v = (t == 0) ? b0
                    : (t == 1) ? b1
                    : (t == 2) ? ((k0 + 6141) & VM1)
                               : ((k0 + 6142) & VM1);
        float4 w = xr[v];
        const int base = v << 2;
        const int o0 = (base     - s) & LM1;
        const int o1 = (base + 1 - s) & LM1;
        const int o2 = (base + 2 - s) & LM1;
        const int o3 = (base + 3 - s) & LM1;
        w.x = (o0 < ML) ? 0.0f : w.x;
        w.y = (o1 < ML) ? 0.0f : w.y;
        w.z = (o2 < ML) ? 0.0f : w.z;
        w.w = (o3 < ML) ? 0.0f : w.w;
        yr[v] = w;
    }
}

extern "C" void kernel_launch(void* const* d_in, const int* in_sizes, int n_in,
                              void* d_out, int out_size)
{
    const float4* x      = (const float4*)d_in[0];
    const int*    starts = (const int*)d_in[1];
    float4*       out    = (float4*)d_out;

    const int n_rows = in_sizes[1];               // 128*12 = 1536
    random_time_mask_kernel<<<n_rows * SPLITS, THREADS>>>(x, starts, out);
}